// round 1
// baseline (speedup 1.0000x reference)
#include <cuda_runtime.h>
#include <cuda_bf16.h>

// Problem: mask_pred (32,16,256,256) fp32, pos_gt (32,16,4) int64.
// loss = -mean( log(mp)*gt + log1p(-mp)*(1-gt) ), gt = inclusive box mask.
// Each element needs exactly one log: log(mp) in-box else log(1-mp).

#define N_IMG   512        // B*R
#define HPIX    256
#define WPIX    256
#define ROWS_PER_BLOCK 64
#define CHUNKS_PER_IMG (HPIX / ROWS_PER_BLOCK)   // 4
#define NBLOCKS (N_IMG * CHUNKS_PER_IMG)          // 2048
#define NTHREADS 256
#define F4_PER_BLOCK (ROWS_PER_BLOCK * WPIX / 4)  // 4096
#define ITERS (F4_PER_BLOCK / NTHREADS)           // 16
#define N_TOTAL 33554432.0                        // 32*16*256*256

__device__ double g_part[NBLOCKS];

__global__ void __launch_bounds__(NTHREADS)
ce_main(const float* __restrict__ mp, const long long* __restrict__ pg) {
    const int blk    = blockIdx.x;
    const int img    = blk >> 2;          // / CHUNKS_PER_IMG
    const int rchunk = blk & 3;

    const long long* box = pg + (size_t)img * 4;
    const int y0 = (int)__ldg(box + 0);
    const int x0 = (int)__ldg(box + 1);
    const int y1 = (int)__ldg(box + 2);
    const int x1 = (int)__ldg(box + 3);

    const float4* base = reinterpret_cast<const float4*>(mp)
                         + (size_t)img * (HPIX * WPIX / 4)
                         + (size_t)rchunk * F4_PER_BLOCK;

    const int tid = threadIdx.x;
    float acc = 0.0f;

    #pragma unroll
    for (int it = 0; it < ITERS; ++it) {
        const int idx = it * NTHREADS + tid;       // 0..4095
        const float4 v = __ldg(base + idx);
        const int r  = idx >> 6;                   // 64 float4 per row
        const int h  = rchunk * ROWS_PER_BLOCK + r;
        const bool rowin = (h >= y0) & (h <= y1);
        const int w0 = (idx & 63) << 2;

        float a0 = (rowin & (w0     >= x0) & (w0     <= x1)) ? v.x : 1.0f - v.x;
        float a1 = (rowin & (w0 + 1 >= x0) & (w0 + 1 <= x1)) ? v.y : 1.0f - v.y;
        float a2 = (rowin & (w0 + 2 >= x0) & (w0 + 2 <= x1)) ? v.z : 1.0f - v.z;
        float a3 = (rowin & (w0 + 3 >= x0) & (w0 + 3 <= x1)) ? v.w : 1.0f - v.w;

        acc += __logf(a0);
        acc += __logf(a1);
        acc += __logf(a2);
        acc += __logf(a3);
    }

    // warp reduce (float)
    #pragma unroll
    for (int off = 16; off; off >>= 1)
        acc += __shfl_down_sync(0xffffffffu, acc, off);

    __shared__ float s[NTHREADS / 32];
    if ((tid & 31) == 0) s[tid >> 5] = acc;
    __syncthreads();

    if (tid < NTHREADS / 32) {
        float v = s[tid];
        #pragma unroll
        for (int off = (NTHREADS / 64); off; off >>= 1)
            v += __shfl_down_sync(0xffu, v, off);
        if (tid == 0) g_part[blk] = (double)v;
    }
}

__global__ void __launch_bounds__(256)
ce_final(float* __restrict__ out) {
    const int tid = threadIdx.x;
    double s = 0.0;
    #pragma unroll
    for (int i = tid; i < NBLOCKS; i += 256)
        s += g_part[i];

    #pragma unroll
    for (int off = 16; off; off >>= 1)
        s += __shfl_down_sync(0xffffffffu, s, off);

    __shared__ double sh[8];
    if ((tid & 31) == 0) sh[tid >> 5] = s;
    __syncthreads();

    if (tid < 8) {
        double v = sh[tid];
        #pragma unroll
        for (int off = 4; off; off >>= 1)
            v += __shfl_down_sync(0xffu, v, off);
        if (tid == 0) out[0] = (float)(-v / N_TOTAL);
    }
}

extern "C" void kernel_launch(void* const* d_in, const int* in_sizes, int n_in,
                              void* d_out, int out_size) {
    const float*     mp = (const float*)d_in[0];
    const long long* pg = (const long long*)d_in[1];
    float*           out = (float*)d_out;
    (void)in_sizes; (void)n_in; (void)out_size;

    ce_main<<<NBLOCKS, NTHREADS>>>(mp, pg);
    ce_final<<<1, 256>>>(out);
}